// round 7
// baseline (speedup 1.0000x reference)
#include <cuda_runtime.h>
#include <math.h>
#include <stdint.h>

#define N_MAX 10000
#define E_MAX 100000

typedef unsigned long long ull;

// Scratch (no cudaMalloc allowed)
__device__ float g_q[N_MAX * 20];          // per-node q
__device__ float g_z[N_MAX];               // softmax denominator
__device__ float g_ex[E_MAX];              // exp(dot) -> sqrt(alpha)
__device__ float g_v[(size_t)E_MAX * 40];  // per-edge v (v_s partial1 + v_v)
__device__ float g_vs2[(size_t)E_MAX * 16];// v_s partial 2 (from B2 blocks)

// ---- packed f32x2 helpers ----
__device__ __forceinline__ ull ffma2(ull a, ull b, ull c) {
    ull d; asm("fma.rn.f32x2 %0, %1, %2, %3;" : "=l"(d) : "l"(a), "l"(b), "l"(c)); return d;
}
__device__ __forceinline__ ull fmul2(ull a, ull b) {
    ull d; asm("mul.rn.f32x2 %0, %1, %2;" : "=l"(d) : "l"(a), "l"(b)); return d;
}
__device__ __forceinline__ ull pack2(float a, float b) {
    ull r; asm("mov.b64 %0, {%1, %2};" : "=l"(r) : "f"(a), "f"(b)); return r;
}
__device__ __forceinline__ void unpack2(ull v, float& lo, float& hi) {
    asm("mov.b64 {%0, %1}, %2;" : "=f"(lo), "=f"(hi) : "l"(v));
}

// ---------------------------------------------------------------------------
// Kernel 0: per-node q projection, zero z and out
// ---------------------------------------------------------------------------
__global__ void __launch_bounds__(64) k_nodes(const float* __restrict__ node_ft,
                        const float* __restrict__ wqs, const float* __restrict__ wqv,
                        float* __restrict__ out, int N)
{
    int n = blockIdx.x * blockDim.x + threadIdx.x;
    if (n >= N) return;
    const float* x = node_ft + (size_t)n * 40;
    float xs[16], xv[24];
#pragma unroll
    for (int i = 0; i < 16; i++) xs[i] = x[i];
#pragma unroll
    for (int i = 0; i < 24; i++) xv[i] = x[16 + i];
    const float s0 = 0.25f, s1 = 0.35355339059327373f;
    float q[20];
#pragma unroll
    for (int o = 0; o < 8; o++) {
        float a = 0.f;
#pragma unroll
        for (int i = 0; i < 16; i++) a += xs[i] * wqs[i * 8 + o];
        q[o] = a * s0;
    }
#pragma unroll
    for (int o = 0; o < 4; o++)
#pragma unroll
        for (int c = 0; c < 3; c++) {
            float a = 0.f;
#pragma unroll
            for (int i = 0; i < 8; i++) a += xv[i * 3 + c] * wqv[i * 4 + o];
            q[8 + o * 3 + c] = a * s1;
        }
#pragma unroll
    for (int i = 0; i < 20; i++) g_q[(size_t)n * 20 + i] = q[i];
    g_z[n] = 0.f;
    float4 z4 = make_float4(0.f, 0.f, 0.f, 0.f);
#pragma unroll
    for (int i = 0; i < 10; i++)
        *reinterpret_cast<float4*>(&out[(size_t)n * 40 + i * 4]) = z4;
}

// ---------------------------------------------------------------------------
// Main kernel: 3 block types, each with a 40KB W2 slice resident in smem.
//   type 0 (A):  wk (fck_w2 cols 0..319)   -> k_s, k_v, dot, exp, atomic z
//   type 1 (B1): wv cols 0..319            -> v_s partial 1 -> g_v[0..15]
//   type 2 (B2): wv cols 320..639          -> v_s partial 2 -> g_vs2, v_v -> g_v[16..39]
// Persistent: each type covers all tiles with stride 148. grid = 444.
// ---------------------------------------------------------------------------
#define SB_W2   0        // 32 x 320
#define SB_WT   10240    // 16 x 320 (per-edge weights)
#define SB_H2   15360    // 32 x 16 floats, edge-packed (byte 61440, 16B aligned)
#define SB_W1   15872    // 512
#define SB_WDS  16384    // 64
#define SB_WDV  16448    // 16
#define SB_ES   16464    // 16 x 16
#define SB_SH   16720    // 16 x 4
#define SB_IX   16784    // 32 ints
#define SB_PF   16816    // 16 x 96
#define SB_KK   18352    // 16 x 20
#define SMEM_FLOATS 18672
#define SMEM_BYTES (SMEM_FLOATS * 4)

__global__ void __launch_bounds__(256, 3) k_edges(
    const float* __restrict__ node_ft,
    const int* __restrict__ eidx,
    const float* __restrict__ edge_sh,
    const float* __restrict__ edge_sc,
    const float* __restrict__ fck_w1,
    const float* __restrict__ fck_w2,
    const float* __restrict__ fcv_w1,
    const float* __restrict__ fcv_w2,
    const float* __restrict__ wdot_s,
    const float* __restrict__ wdot_v,
    int E)
{
    extern __shared__ float sm[];
    const int tid  = threadIdx.x;
    const int type = blockIdx.x % 3;
    const int bslot = blockIdx.x / 3;

    // ---- startup: stage this block's W2 slice + W1 (+ wdot for type A) ----
    {
        const float* W2src = (type == 0) ? fck_w2 : fcv_w2;
        const int ncolsrc = (type == 0) ? 320 : 640;
        const int coloff  = (type == 2) ? 320 : 0;
        for (int i = tid; i < 10240; i += 256) {
            int j = i / 320, c = i - j * 320;
            sm[SB_W2 + i] = W2src[(size_t)j * ncolsrc + coloff + c];
        }
        const float* W1src = (type == 0) ? fck_w1 : fcv_w1;
        for (int i = tid; i < 512; i += 256) sm[SB_W1 + i] = W1src[i];
        if (type == 0) {
            if (tid < 64) sm[SB_WDS + tid] = wdot_s[tid];
            if (tid < 16) sm[SB_WDV + tid] = wdot_v[tid];
        }
    }
    __syncthreads();

    const float ISQ32 = 0.17677669529663687f;   // 1/sqrt(32)
    const float ISQ24 = 0.2041241452319315f;    // 1/sqrt(24)
    const float ISQ3  = 0.5773502691896258f;    // 1/sqrt(3)
    const float ISQ2  = 0.7071067811865476f;    // 1/sqrt(2)

    int* ixs = (int*)(sm + SB_IX);
    int* ixr = (int*)(sm + SB_IX + 16);
    const int ntiles = (E + 15) >> 4;
    const int wid = tid >> 5, lane = tid & 31;

    for (int t = bslot; t < ntiles; t += 148) {
        const int ebase = t << 4;

        // ---- stage edge data ----
        if (tid < 32) {
            int e = tid & 15;
            int eg = min(ebase + e, E - 1);
            if (tid < 16) ixs[e] = eidx[eg];
            else          ixr[e] = eidx[E + eg];
        }
        {
            int e = tid >> 4, i = tid & 15;
            int eg = min(ebase + e, E - 1);
            sm[SB_ES + tid] = edge_sc[(size_t)eg * 16 + i];
        }
        if (tid >= 64 && tid < 128) {
            int f = tid - 64;
            int eg = min(ebase + (f >> 2), E - 1);
            sm[SB_SH + f] = edge_sh[(size_t)eg * 4 + (f & 3)];
        }
        __syncthreads();

        // ---- P1: hidden activations h (silu), edge-packed [j][16e] ----
        float* H2f = sm + SB_H2;
#pragma unroll
        for (int s = 0; s < 2; s++) {
            int task = tid + s * 256;
            int e = task & 15, j = task >> 4;
            const float* es = sm + SB_ES + e * 16;
            const float* W1 = sm + SB_W1;
            float a = 0.f;
#pragma unroll
            for (int i = 0; i < 16; i++) a += es[i] * W1[i * 32 + j];
            a *= 0.25f;                                // 1/sqrt(16)
            H2f[j * 16 + e] = a / (1.f + expf(-a));    // silu
        }
        __syncthreads();

        // ---- P2: w = h @ W2slice / sqrt(32), FFMA2, 160 threads x 2 cols ----
        if (tid < 160) {
            const int col = tid * 2;
            const ull* H2 = (const ull*)(sm + SB_H2);
            ull acc[2][8];
#pragma unroll
            for (int c = 0; c < 2; c++)
#pragma unroll
                for (int p = 0; p < 8; p++) acc[c][p] = 0ull;
#pragma unroll 4
            for (int j = 0; j < 32; j++) {
                float2 w = *reinterpret_cast<const float2*>(sm + SB_W2 + j * 320 + col);
                ull w0 = pack2(w.x, w.x), w1 = pack2(w.y, w.y);
                const ulonglong2* Hj = reinterpret_cast<const ulonglong2*>(H2 + j * 8);
                ulonglong2 hA = Hj[0], hB = Hj[1], hC = Hj[2], hD = Hj[3];
                ull hp[8] = { hA.x, hA.y, hB.x, hB.y, hC.x, hC.y, hD.x, hD.y };
#pragma unroll
                for (int p = 0; p < 8; p++) {
                    acc[0][p] = ffma2(hp[p], w0, acc[0][p]);
                    acc[1][p] = ffma2(hp[p], w1, acc[1][p]);
                }
            }
            ull sc = pack2(ISQ32, ISQ32);
#pragma unroll
            for (int c = 0; c < 2; c++)
#pragma unroll
                for (int p = 0; p < 8; p++) {
                    float lo, hi;
                    unpack2(fmul2(acc[c][p], sc), lo, hi);
                    sm[SB_WT + (2 * p)     * 320 + col + c] = lo;
                    sm[SB_WT + (2 * p + 1) * 320 + col + c] = hi;
                }
        }
        __syncthreads();

        // ---- P3: warp per edge, 2 rounds ----
#pragma unroll
        for (int r = 0; r < 2; r++) {
            const int le = wid * 2 + r;
            const int eg = ebase + le;
            const bool active = (eg < E);
            const int snd = ixs[le];
            const int rcv = ixr[le];
            const float* nf = node_ft + (size_t)snd * 40;
            const float shs  = sm[SB_SH + le * 4 + 0];
            const float shv0 = sm[SB_SH + le * 4 + 1];
            const float shv1 = sm[SB_SH + le * 4 + 2];
            const float shv2 = sm[SB_SH + le * 4 + 3];
            float* P = sm + SB_PF + le * 96;

            // P: XS@0(16) XV@16(24) SHS@40 SHV@41(3) PSS@44(16) PVV@60(8) PXX@68(24)
            if (lane < 16) {
                float xs = nf[lane];
                P[lane]      = xs;
                P[44 + lane] = xs * shs;
            } else if (lane < 24) {
                int i = lane - 16;
                float v0 = nf[16 + i * 3 + 0];
                float v1 = nf[16 + i * 3 + 1];
                float v2 = nf[16 + i * 3 + 2];
                P[16 + i * 3 + 0] = v0; P[16 + i * 3 + 1] = v1; P[16 + i * 3 + 2] = v2;
                P[60 + i] = (v0 * shv0 + v1 * shv1 + v2 * shv2) * ISQ3;
                P[68 + i * 3 + 0] = (v1 * shv2 - v2 * shv1) * ISQ2;
                P[68 + i * 3 + 1] = (v2 * shv0 - v0 * shv2) * ISQ2;
                P[68 + i * 3 + 2] = (v0 * shv1 - v1 * shv0) * ISQ2;
            } else if (lane == 24) {
                P[40] = shs; P[41] = shv0; P[42] = shv1; P[43] = shv2;
            }
            __syncwarp();

            const float* WT = sm + SB_WT + le * 320;

            if (type == 0) {
                // ---- k epilogue: k_s, k_v, dot(q,k), exp, atomic z ----
                float* K = sm + SB_KK + le * 20;
                if (lane < 8) {
                    int o = lane;
                    float acc = 0.f;
#pragma unroll
                    for (int i = 0; i < 16; i++) acc += P[44 + i] * WT[i * 8 + o];
#pragma unroll
                    for (int i = 0; i < 8;  i++) acc += P[60 + i] * WT[128 + i * 8 + o];
                    K[o] = acc * ISQ24;
                } else if (lane < 20) {
                    int tt = lane - 8; int o = tt / 3; int c = tt % 3;
                    float a = 0.f, b = 0.f, cx = 0.f;
#pragma unroll
                    for (int i = 0; i < 16; i++) a  += P[i]              * WT[192 + i * 4 + o];
#pragma unroll
                    for (int i = 0; i < 8;  i++) b  += P[16 + i * 3 + c] * WT[256 + i * 4 + o];
#pragma unroll
                    for (int i = 0; i < 8;  i++) cx += P[68 + i * 3 + c] * WT[288 + i * 4 + o];
                    K[8 + tt] = (P[41 + c] * a + P[40] * b + cx) * ISQ32;
                }
                __syncwarp();

                const float* qr = g_q + (size_t)rcv * 20;
                float d = 0.f;
                {
                    int term = lane;
                    int i = term >> 3, j = term & 7;
                    d += qr[i] * K[j] * sm[SB_WDS + i * 8 + j];
                    term += 32; i = term >> 3; j = term & 7;
                    d += qr[i] * K[j] * sm[SB_WDS + i * 8 + j];
                }
                if (lane < 16) {
                    int i = lane >> 2, j = lane & 3;
                    float s = qr[8 + i * 3 + 0] * K[8 + j * 3 + 0]
                            + qr[8 + i * 3 + 1] * K[8 + j * 3 + 1]
                            + qr[8 + i * 3 + 2] * K[8 + j * 3 + 2];
                    d += s * sm[SB_WDV + i * 4 + j] * ISQ3;
                }
#pragma unroll
                for (int off = 16; off; off >>= 1) d += __shfl_xor_sync(0xffffffffu, d, off);
                if (lane == 0 && active) {
                    d *= 0.11180339887498948f;     // 1/sqrt(80)
                    float ex = expf(d);
                    g_ex[eg] = ex;
                    atomicAdd(&g_z[rcv], ex);
                }
            } else if (type == 1) {
                // ---- v_s partial 1: w1v (16x16) full + w2v i<4 ----
                if (lane < 16) {
                    int o = lane;
                    float acc = 0.f;
#pragma unroll
                    for (int i = 0; i < 16; i++) acc += P[44 + i] * WT[i * 16 + o];
#pragma unroll
                    for (int i = 0; i < 4;  i++) acc += P[60 + i] * WT[256 + i * 16 + o];
                    if (active) g_v[(size_t)eg * 40 + o] = acc * ISQ24;
                }
            } else {
                // ---- v_s partial 2 (w2v i>=4) + full v_v ----
                if (lane < 16) {
                    int o = lane;
                    float acc = 0.f;
#pragma unroll
                    for (int i = 0; i < 4; i++) acc += P[60 + 4 + i] * WT[i * 16 + o];
                    if (active) g_vs2[(size_t)eg * 16 + o] = acc * ISQ24;
                }
                {
                    int tt = (lane >= 16) ? (lane - 16) : (lane + 16);
                    if (tt < 24) {
                        int o = tt / 3, c = tt % 3;
                        float a = 0.f, b = 0.f, cx = 0.f;
#pragma unroll
                        for (int i = 0; i < 16; i++) a  += P[i]              * WT[64  + i * 8 + o];
#pragma unroll
                        for (int i = 0; i < 8;  i++) b  += P[16 + i * 3 + c] * WT[192 + i * 8 + o];
#pragma unroll
                        for (int i = 0; i < 8;  i++) cx += P[68 + i * 3 + c] * WT[256 + i * 8 + o];
                        float vv = (P[41 + c] * a + P[40] * b + cx) * ISQ32;
                        if (active) g_v[(size_t)eg * 40 + 16 + tt] = vv;
                    }
                }
            }
        }
        __syncthreads();
    }
}

// ---------------------------------------------------------------------------
__global__ void k_alpha(const int* __restrict__ eidx, int E)
{
    int e = blockIdx.x * blockDim.x + threadIdx.x;
    if (e >= E) return;
    g_ex[e] = sqrtf(__fdividef(g_ex[e], g_z[eidx[E + e]]));
}

// ---------------------------------------------------------------------------
__global__ void k_scatter(const int* __restrict__ eidx, float* __restrict__ out, int E)
{
    int idx = blockIdx.x * blockDim.x + threadIdx.x;
    int e = idx / 10, q = idx % 10;
    if (e >= E) return;
    int rcv = eidx[E + e];
    float a = g_ex[e];
    float4 v = *reinterpret_cast<const float4*>(&g_v[(size_t)e * 40 + q * 4]);
    if (q < 4) {
        float4 w = *reinterpret_cast<const float4*>(&g_vs2[(size_t)e * 16 + q * 4]);
        v.x += w.x; v.y += w.y; v.z += w.z; v.w += w.w;
    }
    float* dst = &out[(size_t)rcv * 40 + q * 4];
    asm volatile("red.global.add.v4.f32 [%0], {%1, %2, %3, %4};"
                 :: "l"(dst), "f"(a * v.x), "f"(a * v.y), "f"(a * v.z), "f"(a * v.w)
                 : "memory");
}

// ---------------------------------------------------------------------------
extern "C" void kernel_launch(void* const* d_in, const int* in_sizes, int n_in,
                              void* d_out, int out_size)
{
    const float* node_ft = (const float*)d_in[0];
    const int*   eidx    = (const int*)d_in[1];
    const float* edge_sh = (const float*)d_in[2];
    const float* edge_sc = (const float*)d_in[3];
    const float* wqs     = (const float*)d_in[4];
    const float* wqv     = (const float*)d_in[5];
    const float* fck_w1  = (const float*)d_in[6];
    const float* fck_w2  = (const float*)d_in[7];
    const float* fcv_w1  = (const float*)d_in[8];
    const float* fcv_w2  = (const float*)d_in[9];
    const float* wdot_s  = (const float*)d_in[10];
    const float* wdot_v  = (const float*)d_in[11];
    float* out = (float*)d_out;

    int N = in_sizes[0] / 40;
    int E = in_sizes[1] / 2;

    cudaFuncSetAttribute(k_edges, cudaFuncAttributeMaxDynamicSharedMemorySize, SMEM_BYTES);

    k_nodes<<<(N + 63) / 64, 64>>>(node_ft, wqs, wqv, out, N);
    k_edges<<<444, 256, SMEM_BYTES>>>(node_ft, eidx, edge_sh, edge_sc,
                                      fck_w1, fck_w2, fcv_w1, fcv_w2,
                                      wdot_s, wdot_v, E);
    k_alpha<<<(E + 255) / 256, 256>>>(eidx, E);
    k_scatter<<<((long long)E * 10 + 255) / 256, 256>>>(eidx, out, E);
}

// round 8
// speedup vs baseline: 1.4549x; 1.4549x over previous
#include <cuda_runtime.h>
#include <math.h>

#define N_MAX 10000
#define E_MAX 100000

// Scratch (no cudaMalloc allowed)
__device__ float g_q[N_MAX * 20];         // per-node q: 8 scalar + 4*3 vector
__device__ float g_z[N_MAX];              // softmax denominator
__device__ float g_ex[E_MAX];             // per-edge exp(dot) -> sqrt(alpha)
__device__ float g_v[(size_t)E_MAX * 40]; // per-edge v: 16 scalar + 8*3 vector

// ---------------------------------------------------------------------------
// Kernel 0: per-node q projection, zero z and out
// ---------------------------------------------------------------------------
__global__ void __launch_bounds__(64) k_nodes(const float* __restrict__ node_ft,
                        const float* __restrict__ wqs,   // [16,8]
                        const float* __restrict__ wqv,   // [8,4]
                        float* __restrict__ out, int N)
{
    int n = blockIdx.x * blockDim.x + threadIdx.x;
    if (n >= N) return;
    const float* x = node_ft + (size_t)n * 40;
    float xs[16], xv[24];
#pragma unroll
    for (int i = 0; i < 16; i++) xs[i] = x[i];
#pragma unroll
    for (int i = 0; i < 24; i++) xv[i] = x[16 + i];

    const float s0 = 0.25f;                   // 1/sqrt(16)
    const float s1 = 0.35355339059327373f;    // 1/sqrt(8)
    float q[20];
#pragma unroll
    for (int o = 0; o < 8; o++) {
        float acc = 0.f;
#pragma unroll
        for (int i = 0; i < 16; i++) acc += xs[i] * wqs[i * 8 + o];
        q[o] = acc * s0;
    }
#pragma unroll
    for (int o = 0; o < 4; o++) {
#pragma unroll
        for (int c = 0; c < 3; c++) {
            float acc = 0.f;
#pragma unroll
            for (int i = 0; i < 8; i++) acc += xv[i * 3 + c] * wqv[i * 4 + o];
            q[8 + o * 3 + c] = acc * s1;
        }
    }
#pragma unroll
    for (int i = 0; i < 20; i++) g_q[(size_t)n * 20 + i] = q[i];
    g_z[n] = 0.f;
    float4 z4 = make_float4(0.f, 0.f, 0.f, 0.f);
#pragma unroll
    for (int i = 0; i < 10; i++)
        *reinterpret_cast<float4*>(&out[(size_t)n * 40 + i * 4]) = z4;
}

// ---------------------------------------------------------------------------
// Kernel 1: per-edge main work — EXACT R2 structure (best known).
//   Block = 256 threads handles 8 edges.
// ---------------------------------------------------------------------------
__global__ void __launch_bounds__(256) k_edges(
    const float* __restrict__ node_ft,
    const int* __restrict__ eidx,            // [2,E] int32
    const float* __restrict__ edge_sh,       // [E,4]
    const float* __restrict__ edge_sc,       // [E,16]
    const float* __restrict__ fck_w1,        // [16,32]
    const float* __restrict__ fck_w2,        // [32,320]
    const float* __restrict__ fcv_w1,        // [16,32]
    const float* __restrict__ fcv_w2,        // [32,640]
    const float* __restrict__ wdot_s,        // [8,8]
    const float* __restrict__ wdot_v,        // [4,4]
    int E)
{
    __shared__ float sh_h[8][64];     // [edge][ h_k(0..31) | h_v(32..63) ]
    __shared__ float sh_wk[8][320];
    __shared__ float sh_wv[8][640];
    __shared__ float sh_p[8][96];     // XS@0(16) XV@16(24) SHS@40 SHV@41(3) PSS@44(16) PVV@60(8) PXX@68(24)
    __shared__ float sh_k[8][20];     // k_s(8) + k_v(12)

    const int tid   = threadIdx.x;
    const int ebase = blockIdx.x * 8;

    // ---- Phase 1: hidden activations (512 tasks) ----
    for (int task = tid; task < 512; task += 256) {
        int e  = task >> 6;
        int jj = task & 63;
        int eg = min(ebase + e, E - 1);
        const float* es = edge_sc + (size_t)eg * 16;
        const float* W1 = (jj < 32) ? fck_w1 : fcv_w1;
        int j = jj & 31;
        float acc = 0.f;
#pragma unroll
        for (int i = 0; i < 16; i++) acc += es[i] * W1[i * 32 + j];
        acc *= 0.25f;                               // 1/sqrt(16)
        sh_h[e][jj] = acc / (1.f + expf(-acc));     // silu
    }
    __syncthreads();

    // ---- Phase 2: weight generation, register-blocked over 8 edges ----
    const float isq32 = 0.17677669529663687f;       // 1/sqrt(32)
    if (tid < 240) {
        const float* W2; int col, ncol, hoff;
        if (tid < 80) { W2 = fck_w2; col = tid * 4;        ncol = 320; hoff = 0;  }
        else          { W2 = fcv_w2; col = (tid - 80) * 4; ncol = 640; hoff = 32; }
        float4 acc[8];
#pragma unroll
        for (int e = 0; e < 8; e++) acc[e] = make_float4(0.f, 0.f, 0.f, 0.f);
        for (int j = 0; j < 32; j++) {
            float4 w = *reinterpret_cast<const float4*>(W2 + (size_t)j * ncol + col);
#pragma unroll
            for (int e = 0; e < 8; e++) {
                float h = sh_h[e][hoff + j];
                acc[e].x += h * w.x; acc[e].y += h * w.y;
                acc[e].z += h * w.z; acc[e].w += h * w.w;
            }
        }
#pragma unroll
        for (int e = 0; e < 8; e++) {
            float4 r = acc[e];
            r.x *= isq32; r.y *= isq32; r.z *= isq32; r.w *= isq32;
            if (tid < 80) *reinterpret_cast<float4*>(&sh_wk[e][col]) = r;
            else          *reinterpret_cast<float4*>(&sh_wv[e][col]) = r;
        }
    }
    __syncthreads();

    // ---- Phase 3: warp per edge ----
    const int wid  = tid >> 5;
    const int lane = tid & 31;
    const int eg   = ebase + wid;
    const bool active = (eg < E);
    const int egc  = min(eg, E - 1);
    const int snd = eidx[egc];
    const int rcv = eidx[E + egc];
    const float* nf = node_ft + (size_t)snd * 40;
    const float shs  = edge_sh[(size_t)egc * 4 + 0];
    const float shv0 = edge_sh[(size_t)egc * 4 + 1];
    const float shv1 = edge_sh[(size_t)egc * 4 + 2];
    const float shv2 = edge_sh[(size_t)egc * 4 + 3];
    float* P = sh_p[wid];

    if (lane < 16) {
        float xs = nf[lane];
        P[lane]      = xs;
        P[44 + lane] = xs * shs;                    // p_ss
    } else if (lane < 24) {
        int i = lane - 16;
        float v0 = nf[16 + i * 3 + 0];
        float v1 = nf[16 + i * 3 + 1];
        float v2 = nf[16 + i * 3 + 2];
        P[16 + i * 3 + 0] = v0; P[16 + i * 3 + 1] = v1; P[16 + i * 3 + 2] = v2;
        P[60 + i] = (v0 * shv0 + v1 * shv1 + v2 * shv2) * 0.5773502691896258f; // p_vv /sqrt3
        const float is2 = 0.7071067811865476f;      // 1/sqrt(2)
        P[68 + i * 3 + 0] = (v1 * shv2 - v2 * shv1) * is2;   // cross(xv, shv)/sqrt2
        P[68 + i * 3 + 1] = (v2 * shv0 - v0 * shv2) * is2;
        P[68 + i * 3 + 2] = (v0 * shv1 - v1 * shv0) * is2;
    } else if (lane == 24) {
        P[40] = shs; P[41] = shv0; P[42] = shv1; P[43] = shv2;
    }
    __syncwarp();

    const float* WK = sh_wk[wid];
    const float* WV = sh_wv[wid];
    float* K = sh_k[wid];
    const float isq24 = 0.2041241452319315f;        // 1/sqrt(24)

    // k_s (lanes 0..7), k_v (lanes 8..19)
    if (lane < 8) {
        int o = lane;
        float acc = 0.f;
#pragma unroll
        for (int i = 0; i < 16; i++) acc += P[44 + i] * WK[i * 8 + o];
#pragma unroll
        for (int i = 0; i < 8;  i++) acc += P[60 + i] * WK[128 + i * 8 + o];
        K[o] = acc * isq24;
    } else if (lane < 20) {
        int t = lane - 8; int o = t / 3; int c = t % 3;
        float a = 0.f, b = 0.f, cx = 0.f;
#pragma unroll
        for (int i = 0; i < 16; i++) a  += P[i]              * WK[192 + i * 4 + o];
#pragma unroll
        for (int i = 0; i < 8;  i++) b  += P[16 + i * 3 + c] * WK[256 + i * 4 + o];
#pragma unroll
        for (int i = 0; i < 8;  i++) cx += P[68 + i * 3 + c] * WK[288 + i * 4 + o];
        K[8 + t] = (P[41 + c] * a + P[40] * b + cx) * isq32;
    }

    // v_s (lanes 0..15)
    if (lane < 16) {
        int o = lane;
        float acc = 0.f;
#pragma unroll
        for (int i = 0; i < 16; i++) acc += P[44 + i] * WV[i * 16 + o];
#pragma unroll
        for (int i = 0; i < 8;  i++) acc += P[60 + i] * WV[256 + i * 16 + o];
        if (active) g_v[(size_t)eg * 40 + o] = acc * isq24;
    }
    // v_v: 24 comps. lanes 16..31 -> t=0..15, lanes 0..7 -> t=16..23
    {
        int t = (lane >= 16) ? (lane - 16) : (lane + 16);
        if (t < 24) {
            int o = t / 3, c = t % 3;
            float a = 0.f, b = 0.f, cx = 0.f;
#pragma unroll
            for (int i = 0; i < 16; i++) a  += P[i]              * WV[384 + i * 8 + o];
#pragma unroll
            for (int i = 0; i < 8;  i++) b  += P[16 + i * 3 + c] * WV[512 + i * 8 + o];
#pragma unroll
            for (int i = 0; i < 8;  i++) cx += P[68 + i * 3 + c] * WV[576 + i * 8 + o];
            float vv = (P[41 + c] * a + P[40] * b + cx) * isq32;
            if (active) g_v[(size_t)eg * 40 + 16 + t] = vv;
        }
    }
    __syncwarp();

    // dot(q[recv], k)
    const float* qr = g_q + (size_t)rcv * 20;
    float d = 0.f;
    {
        int term = lane;
        int i = term >> 3, j = term & 7;
        d += qr[i] * K[j] * wdot_s[i * 8 + j];
        term += 32; i = term >> 3; j = term & 7;
        d += qr[i] * K[j] * wdot_s[i * 8 + j];
    }
    if (lane < 16) {
        int i = lane >> 2, j = lane & 3;
        float s = qr[8 + i * 3 + 0] * K[8 + j * 3 + 0]
                + qr[8 + i * 3 + 1] * K[8 + j * 3 + 1]
                + qr[8 + i * 3 + 2] * K[8 + j * 3 + 2];
        d += s * wdot_v[i * 4 + j] * 0.5773502691896258f;   // 1/sqrt(3)
    }
#pragma unroll
    for (int off = 16; off; off >>= 1) d += __shfl_xor_sync(0xffffffffu, d, off);
    if (lane == 0 && active) {
        d *= 0.11180339887498948f;                 // 1/sqrt(80)
        float ex = expf(d);
        g_ex[eg] = ex;
        atomicAdd(&g_z[rcv], ex);
    }
}

// ---------------------------------------------------------------------------
// Kernel 2: alpha = sqrt(ex / z[rcv])  (in place into g_ex)
// ---------------------------------------------------------------------------
__global__ void k_alpha(const int* __restrict__ eidx, int E)
{
    int e = blockIdx.x * blockDim.x + threadIdx.x;
    if (e >= E) return;
    g_ex[e] = sqrtf(__fdividef(g_ex[e], g_z[eidx[E + e]]));
}

// ---------------------------------------------------------------------------
// Kernel 3: scatter-add with vector reductions (4 floats per red op)
// ---------------------------------------------------------------------------
__global__ void k_scatter(const int* __restrict__ eidx,
                          float* __restrict__ out, int E)
{
    int idx = blockIdx.x * blockDim.x + threadIdx.x;
    int e = idx / 10;
    int q = idx % 10;
    if (e >= E) return;
    int rcv = eidx[E + e];
    float a = g_ex[e];
    float4 v = *reinterpret_cast<const float4*>(&g_v[(size_t)e * 40 + q * 4]);
    float* dst = &out[(size_t)rcv * 40 + q * 4];
    asm volatile("red.global.add.v4.f32 [%0], {%1, %2, %3, %4};"
                 :: "l"(dst), "f"(a * v.x), "f"(a * v.y), "f"(a * v.z), "f"(a * v.w)
                 : "memory");
}

// ---------------------------------------------------------------------------
extern "C" void kernel_launch(void* const* d_in, const int* in_sizes, int n_in,
                              void* d_out, int out_size)
{
    const float* node_ft = (const float*)d_in[0];
    const int*   eidx    = (const int*)d_in[1];
    const float* edge_sh = (const float*)d_in[2];
    const float* edge_sc = (const float*)d_in[3];
    const float* wqs     = (const float*)d_in[4];
    const float* wqv     = (const float*)d_in[5];
    const float* fck_w1  = (const float*)d_in[6];
    const float* fck_w2  = (const float*)d_in[7];
    const float* fcv_w1  = (const float*)d_in[8];
    const float* fcv_w2  = (const float*)d_in[9];
    const float* wdot_s  = (const float*)d_in[10];
    const float* wdot_v  = (const float*)d_in[11];
    float* out = (float*)d_out;

    int N = in_sizes[0] / 40;
    int E = in_sizes[1] / 2;

    k_nodes<<<(N + 63) / 64, 64>>>(node_ft, wqs, wqv, out, N);
    k_edges<<<(E + 7) / 8, 256>>>(node_ft, eidx, edge_sh, edge_sc,
                                  fck_w1, fck_w2, fcv_w1, fcv_w2,
                                  wdot_s, wdot_v, E);
    k_alpha<<<(E + 255) / 256, 256>>>(eidx, E);
    k_scatter<<<((long long)E * 10 + 255) / 256, 256>>>(eidx, out, E);
}

// round 9
// speedup vs baseline: 1.6351x; 1.1239x over previous
#include <cuda_runtime.h>
#include <math.h>
#include <stdint.h>

#define N_MAX 10000
#define E_MAX 100000

// Scratch (no cudaMalloc allowed)
__device__ float g_q[N_MAX * 20];
__device__ float g_z[N_MAX];
__device__ float g_ex[E_MAX];
__device__ float g_v[(size_t)E_MAX * 40];
__device__ uint32_t g_bk[32 * 328];   // W2k tf32 bits, [k][n] pitch 328
__device__ uint32_t g_bv[32 * 648];   // W2v tf32 bits, [k][n] pitch 648

__device__ __forceinline__ uint32_t cvt_tf32(float x) {
    uint32_t r; asm("cvt.rna.tf32.f32 %0, %1;" : "=r"(r) : "f"(x)); return r;
}

// ---------------------------------------------------------------------------
// Prep: convert W2 to tf32 bit layout with conflict-free pitches
// ---------------------------------------------------------------------------
__global__ void k_prep(const float* __restrict__ fck_w2, const float* __restrict__ fcv_w2)
{
    int idx = blockIdx.x * blockDim.x + threadIdx.x;
    if (idx < 32 * 328) {
        int k = idx / 328, n = idx % 328;
        g_bk[idx] = (n < 320) ? cvt_tf32(fck_w2[k * 320 + n]) : 0u;
    }
    idx -= 32 * 328;
    if (idx >= 0 && idx < 32 * 648) {
        int k = idx / 648, n = idx % 648;
        g_bv[idx] = (n < 640) ? cvt_tf32(fcv_w2[k * 640 + n]) : 0u;
    }
}

// ---------------------------------------------------------------------------
// Kernel 0: per-node q projection, zero z and out
// ---------------------------------------------------------------------------
__global__ void __launch_bounds__(64) k_nodes(const float* __restrict__ node_ft,
                        const float* __restrict__ wqs, const float* __restrict__ wqv,
                        float* __restrict__ out, int N)
{
    int n = blockIdx.x * blockDim.x + threadIdx.x;
    if (n >= N) return;
    const float* x = node_ft + (size_t)n * 40;
    float xs[16], xv[24];
#pragma unroll
    for (int i = 0; i < 16; i++) xs[i] = x[i];
#pragma unroll
    for (int i = 0; i < 24; i++) xv[i] = x[16 + i];
    const float s0 = 0.25f, s1 = 0.35355339059327373f;
    float q[20];
#pragma unroll
    for (int o = 0; o < 8; o++) {
        float a = 0.f;
#pragma unroll
        for (int i = 0; i < 16; i++) a += xs[i] * wqs[i * 8 + o];
        q[o] = a * s0;
    }
#pragma unroll
    for (int o = 0; o < 4; o++)
#pragma unroll
        for (int c = 0; c < 3; c++) {
            float a = 0.f;
#pragma unroll
            for (int i = 0; i < 8; i++) a += xv[i * 3 + c] * wqv[i * 4 + o];
            q[8 + o * 3 + c] = a * s1;
        }
#pragma unroll
    for (int i = 0; i < 20; i++) g_q[(size_t)n * 20 + i] = q[i];
    g_z[n] = 0.f;
    float4 z4 = make_float4(0.f, 0.f, 0.f, 0.f);
#pragma unroll
    for (int i = 0; i < 10; i++)
        *reinterpret_cast<float4*>(&out[(size_t)n * 40 + i * 4]) = z4;
}

// ---------------------------------------------------------------------------
// Main kernel: persistent, 16 edges/tile, mma.sync tf32 weight-gen.
// smem float offsets:
#define SB_BK  0          // 32 x 328 (tf32 bits)
#define SB_BV  10496      // 32 x 648
#define SB_W   31232      // 16 x 968 (w per edge: k at 0..319, v at 320..959)
#define SB_HK  46720      // 16 x 33 (tf32 bits)
#define SB_HV  47248      // 16 x 33
#define SB_W1K 47776      // 512
#define SB_W1V 48288      // 512
#define SB_WDS 48800      // 64
#define SB_WDV 48864      // 16
#define SB_ES  48880      // 16 x 16
#define SB_SH  49136      // 16 x 4
#define SB_IX  49200      // 32 ints
#define SB_P   49232      // 16 x 96
#define SB_K   50768      // 16 x 20
#define SMEM_FLOATS 51088
#define SMEM_BYTES (SMEM_FLOATS * 4)
#define WP 968

__global__ void __launch_bounds__(512, 1) k_edges(
    const float* __restrict__ node_ft,
    const int* __restrict__ eidx,
    const float* __restrict__ edge_sh,
    const float* __restrict__ edge_sc,
    const float* __restrict__ fck_w1,
    const float* __restrict__ fcv_w1,
    const float* __restrict__ wdot_s,
    const float* __restrict__ wdot_v,
    int E)
{
    extern __shared__ float sm[];
    const int tid  = threadIdx.x;
    const int wid  = tid >> 5;
    const int lane = tid & 31;

    // ---- startup: stage B (tf32 W2), W1, wdot ----
    {
        uint32_t* bk = (uint32_t*)(sm + SB_BK);
        uint32_t* bv = (uint32_t*)(sm + SB_BV);
        for (int i = tid; i < 32 * 328; i += 512) bk[i] = g_bk[i];
        for (int i = tid; i < 32 * 648; i += 512) bv[i] = g_bv[i];
        if (tid < 512) sm[SB_W1K + tid] = fck_w1[tid];
        else { }
        for (int i = tid; i < 512; i += 512) sm[SB_W1V + i] = fcv_w1[i];
        if (tid < 64) sm[SB_WDS + tid] = wdot_s[tid];
        if (tid < 16) sm[SB_WDV + tid] = wdot_v[tid];
    }
    __syncthreads();

    const float ISQ32 = 0.17677669529663687f;
    const float ISQ24 = 0.2041241452319315f;
    const float ISQ3  = 0.5773502691896258f;
    const float ISQ2  = 0.7071067811865476f;

    int* ixs = (int*)(sm + SB_IX);
    int* ixr = (int*)(sm + SB_IX + 16);
    const int ntiles = (E + 15) >> 4;

    for (int t = blockIdx.x; t < ntiles; t += 148) {
        const int ebase = t << 4;

        // ---- stage edge data (single pass, 512 threads) ----
        if (tid < 256) {
            int e = tid >> 4, i = tid & 15;
            int eg = min(ebase + e, E - 1);
            sm[SB_ES + tid] = edge_sc[(size_t)eg * 16 + i];
        } else if (tid < 288) {
            int f = tid - 256;
            int e = f & 15;
            int eg = min(ebase + e, E - 1);
            if (f < 16) ixs[e] = eidx[eg];
            else        ixr[e] = eidx[E + eg];
        } else if (tid < 352) {
            int f = tid - 288;
            int eg = min(ebase + (f >> 2), E - 1);
            sm[SB_SH + f] = edge_sh[(size_t)eg * 4 + (f & 3)];
        }
        __syncthreads();

        // ---- P1: hidden activations -> tf32 bits in HK/HV ----
        uint32_t* HK = (uint32_t*)(sm + SB_HK);
        uint32_t* HV = (uint32_t*)(sm + SB_HV);
#pragma unroll
        for (int s = 0; s < 2; s++) {
            int task = tid + s * 512;
            int e = task >> 6, jj = task & 63, j = jj & 31;
            const float* W1 = sm + ((jj < 32) ? SB_W1K : SB_W1V);
            const float* es = sm + SB_ES + e * 16;
            float a = 0.f;
#pragma unroll
            for (int i = 0; i < 16; i++) a += es[i] * W1[i * 32 + j];
            a *= 0.25f;
            float h = a / (1.f + expf(-a));
            uint32_t hb = cvt_tf32(h);
            if (jj < 32) HK[e * 33 + j] = hb;
            else         HV[e * 33 + j] = hb;
        }
        __syncthreads();

        // ---- P2: mma.sync tf32 weight-gen ----
        // warps 0..4: k-branch (320 cols), warps 5..14: v-branch (640 cols)
        if (wid < 15) {
            const bool isv = (wid >= 5);
            const uint32_t* Hs = isv ? HV : HK;
            const uint32_t* Bs = (const uint32_t*)(sm + (isv ? SB_BV : SB_BK));
            const int pitch = isv ? 648 : 328;
            const int nbase = isv ? (wid - 5) * 64 : wid * 64;   // within branch
            const int wcol0 = isv ? 320 + nbase : nbase;         // within w row
            const int tq = lane >> 2, tr = lane & 3;

            uint32_t a[4][4];
#pragma unroll
            for (int kc = 0; kc < 4; kc++) {
                int k0 = kc * 8;
                a[kc][0] = Hs[tq * 33 + k0 + tr];
                a[kc][1] = Hs[(tq + 8) * 33 + k0 + tr];
                a[kc][2] = Hs[tq * 33 + k0 + tr + 4];
                a[kc][3] = Hs[(tq + 8) * 33 + k0 + tr + 4];
            }
#pragma unroll
            for (int nc = 0; nc < 8; nc++) {
                int n0 = nbase + nc * 8;
                float c0 = 0.f, c1 = 0.f, c2 = 0.f, c3 = 0.f;
#pragma unroll
                for (int kc = 0; kc < 4; kc++) {
                    uint32_t b0 = Bs[(kc * 8 + tr) * pitch + n0 + tq];
                    uint32_t b1 = Bs[(kc * 8 + tr + 4) * pitch + n0 + tq];
                    asm volatile(
                        "mma.sync.aligned.m16n8k8.row.col.f32.tf32.tf32.f32 "
                        "{%0,%1,%2,%3}, {%4,%5,%6,%7}, {%8,%9}, {%0,%1,%2,%3};"
                        : "+f"(c0), "+f"(c1), "+f"(c2), "+f"(c3)
                        : "r"(a[kc][0]), "r"(a[kc][1]), "r"(a[kc][2]), "r"(a[kc][3]),
                          "r"(b0), "r"(b1));
                }
                float* W = sm + SB_W;
                int col = wcol0 + nc * 8 + 2 * tr;
                *reinterpret_cast<float2*>(&W[tq * WP + col]) =
                    make_float2(c0 * ISQ32, c1 * ISQ32);
                *reinterpret_cast<float2*>(&W[(tq + 8) * WP + col]) =
                    make_float2(c2 * ISQ32, c3 * ISQ32);
            }
        }
        __syncthreads();

        // ---- P3: warp per edge (16 warps, 16 edges) ----
        {
            const int le = wid;
            const int eg = ebase + le;
            const bool active = (eg < E);
            const int snd = ixs[le];
            const int rcv = ixr[le];
            const float* nf = node_ft + (size_t)snd * 40;
            const float shs  = sm[SB_SH + le * 4 + 0];
            const float shv0 = sm[SB_SH + le * 4 + 1];
            const float shv1 = sm[SB_SH + le * 4 + 2];
            const float shv2 = sm[SB_SH + le * 4 + 3];
            float* P = sm + SB_P + le * 96;

            if (lane < 16) {
                float xs = nf[lane];
                P[lane]      = xs;
                P[44 + lane] = xs * shs;
            } else if (lane < 24) {
                int i = lane - 16;
                float v0 = nf[16 + i * 3 + 0];
                float v1 = nf[16 + i * 3 + 1];
                float v2 = nf[16 + i * 3 + 2];
                P[16 + i * 3 + 0] = v0; P[16 + i * 3 + 1] = v1; P[16 + i * 3 + 2] = v2;
                P[60 + i] = (v0 * shv0 + v1 * shv1 + v2 * shv2) * ISQ3;
                P[68 + i * 3 + 0] = (v1 * shv2 - v2 * shv1) * ISQ2;
                P[68 + i * 3 + 1] = (v2 * shv0 - v0 * shv2) * ISQ2;
                P[68 + i * 3 + 2] = (v0 * shv1 - v1 * shv0) * ISQ2;
            } else if (lane == 24) {
                P[40] = shs; P[41] = shv0; P[42] = shv1; P[43] = shv2;
            }
            __syncwarp();

            const float* WK = sm + SB_W + le * WP;
            const float* WV = WK + 320;
            float* K = sm + SB_K + le * 20;

            if (lane < 8) {
                int o = lane;
                float acc = 0.f;
#pragma unroll
                for (int i = 0; i < 16; i++) acc += P[44 + i] * WK[i * 8 + o];
#pragma unroll
                for (int i = 0; i < 8;  i++) acc += P[60 + i] * WK[128 + i * 8 + o];
                K[o] = acc * ISQ24;
            } else if (lane < 20) {
                int tt = lane - 8; int o = tt / 3; int c = tt % 3;
                float a = 0.f, b = 0.f, cx = 0.f;
#pragma unroll
                for (int i = 0; i < 16; i++) a  += P[i]              * WK[192 + i * 4 + o];
#pragma unroll
                for (int i = 0; i < 8;  i++) b  += P[16 + i * 3 + c] * WK[256 + i * 4 + o];
#pragma unroll
                for (int i = 0; i < 8;  i++) cx += P[68 + i * 3 + c] * WK[288 + i * 4 + o];
                K[8 + tt] = (P[41 + c] * a + P[40] * b + cx) * ISQ32;
            }

            if (lane < 16) {
                int o = lane;
                float acc = 0.f;
#pragma unroll
                for (int i = 0; i < 16; i++) acc += P[44 + i] * WV[i * 16 + o];
#pragma unroll
                for (int i = 0; i < 8;  i++) acc += P[60 + i] * WV[256 + i * 16 + o];
                if (active) g_v[(size_t)eg * 40 + o] = acc * ISQ24;
            }
            {
                int tt = (lane >= 16) ? (lane - 16) : (lane + 16);
                if (tt < 24) {
                    int o = tt / 3, c = tt % 3;
                    float a = 0.f, b = 0.f, cx = 0.f;
#pragma unroll
                    for (int i = 0; i < 16; i++) a  += P[i]              * WV[384 + i * 8 + o];
#pragma unroll
                    for (int i = 0; i < 8;  i++) b  += P[16 + i * 3 + c] * WV[512 + i * 8 + o];
#pragma unroll
                    for (int i = 0; i < 8;  i++) cx += P[68 + i * 3 + c] * WV[576 + i * 8 + o];
                    float vv = (P[41 + c] * a + P[40] * b + cx) * ISQ32;
                    if (active) g_v[(size_t)eg * 40 + 16 + tt] = vv;
                }
            }
            __syncwarp();

            const float* qr = g_q + (size_t)rcv * 20;
            float d = 0.f;
            {
                int term = lane;
                int i = term >> 3, j = term & 7;
                d += qr[i] * K[j] * sm[SB_WDS + i * 8 + j];
                term += 32; i = term >> 3; j = term & 7;
                d += qr[i] * K[j] * sm[SB_WDS + i * 8 + j];
            }
            if (lane < 16) {
                int i = lane >> 2, j = lane & 3;
                float s = qr[8 + i * 3 + 0] * K[8 + j * 3 + 0]
                        + qr[8 + i * 3 + 1] * K[8 + j * 3 + 1]
                        + qr[8 + i * 3 + 2] * K[8 + j * 3 + 2];
                d += s * sm[SB_WDV + i * 4 + j] * ISQ3;
            }
#pragma unroll
            for (int off = 16; off; off >>= 1) d += __shfl_xor_sync(0xffffffffu, d, off);
            if (lane == 0 && active) {
                d *= 0.11180339887498948f;
                float ex = expf(d);
                g_ex[eg] = ex;
                atomicAdd(&g_z[rcv], ex);
            }
        }
        __syncthreads();
    }
}

// ---------------------------------------------------------------------------
__global__ void k_alpha(const int* __restrict__ eidx, int E)
{
    int e = blockIdx.x * blockDim.x + threadIdx.x;
    if (e >= E) return;
    g_ex[e] = sqrtf(__fdividef(g_ex[e], g_z[eidx[E + e]]));
}

// ---------------------------------------------------------------------------
__global__ void k_scatter(const int* __restrict__ eidx, float* __restrict__ out, int E)
{
    int idx = blockIdx.x * blockDim.x + threadIdx.x;
    int e = idx / 10, q = idx % 10;
    if (e >= E) return;
    int rcv = eidx[E + e];
    float a = g_ex[e];
    float4 v = *reinterpret_cast<const float4*>(&g_v[(size_t)e * 40 + q * 4]);
    float* dst = &out[(size_t)rcv * 40 + q * 4];
    asm volatile("red.global.add.v4.f32 [%0], {%1, %2, %3, %4};"
                 :: "l"(dst), "f"(a * v.x), "f"(a * v.y), "f"(a * v.z), "f"(a * v.w)
                 : "memory");
}

// ---------------------------------------------------------------------------
extern "C" void kernel_launch(void* const* d_in, const int* in_sizes, int n_in,
                              void* d_out, int out_size)
{
    const float* node_ft = (const float*)d_in[0];
    const int*   eidx    = (const int*)d_in[1];
    const float* edge_sh = (const float*)d_in[2];
    const float* edge_sc = (const float*)d_in[3];
    const float* wqs     = (const float*)d_in[4];
    const float* wqv     = (const float*)d_in[5];
    const float* fck_w1  = (const float*)d_in[6];
    const float* fck_w2  = (const float*)d_in[7];
    const float* fcv_w1  = (const float*)d_in[8];
    const float* fcv_w2  = (const float*)d_in[9];
    const float* wdot_s  = (const float*)d_in[10];
    const float* wdot_v  = (const float*)d_in[11];
    float* out = (float*)d_out;

    int N = in_sizes[0] / 40;
    int E = in_sizes[1] / 2;

    cudaFuncSetAttribute(k_edges, cudaFuncAttributeMaxDynamicSharedMemorySize, SMEM_BYTES);

    k_prep<<<(32 * 328 + 32 * 648 + 255) / 256, 256>>>(fck_w2, fcv_w2);
    k_nodes<<<(N + 63) / 64, 64>>>(node_ft, wqs, wqv, out, N);
    k_edges<<<148, 512, SMEM_BYTES>>>(node_ft, eidx, edge_sh, edge_sc,
                                      fck_w1, fcv_w1, wdot_s, wdot_v, E);
    k_alpha<<<(E + 255) / 256, 256>>>(eidx, E);
    k_scatter<<<((long long)E * 10 + 255) / 256, 256>>>(eidx, out, E);
}